// round 7
// baseline (speedup 1.0000x reference)
#include <cuda_runtime.h>
#include <math.h>
#include <stdint.h>

#define D_MODEL 1024
#define NH      16
#define HD      64
#define B_      2
#define T_      2048
#define BT      4096
#define BH      32

// ------------------------- device scratch (no allocs) ----------------------
__device__ float g_x  [BT * D_MODEL];      // x, tf32-rounded
__device__ float g_q  [BH * T_ * HD];      // [bh][t][dd]   (tf32)
__device__ float g_k  [BH * T_ * HD];      // [bh][s][dd]   (tf32)
__device__ float g_v  [BH * T_ * HD];      // [bh][t][dd]   (exact)
__device__ float g_vt [BH * HD * T_];      // [bh][dd][t]   (tf32)
__device__ float g_ao [BT * D_MODEL];      // [b*t][D]      (tf32)
__device__ float g_wt [3 * D_MODEL * D_MODEL];   // Wqkv^T (tf32)
__device__ float g_wot[D_MODEL * D_MODEL];       // Wo^T   (tf32)
__device__ float g_rowsum[BH * T_];

// ------------------------------ helpers ------------------------------------
__device__ __forceinline__ uint32_t s2u(const void* p) {
    return (uint32_t)__cvta_generic_to_shared(p);
}
__device__ __forceinline__ void cpa16(uint32_t d, const void* g) {
    asm volatile("cp.async.cg.shared.global [%0], [%1], 16;" :: "r"(d), "l"(g));
}
__device__ __forceinline__ void cpcommit() { asm volatile("cp.async.commit_group;"); }
template <int N> __device__ __forceinline__ void cpwait() {
    asm volatile("cp.async.wait_group %0;" :: "n"(N));
}
__device__ __forceinline__ float f2tf(float f) {
    uint32_t r; asm("cvt.rna.tf32.f32 %0, %1;" : "=r"(r) : "f"(f));
    return __uint_as_float(r);
}
// m16n8k8 tf32 mma, fp32 accumulate (operands pre-rounded)
__device__ __forceinline__ void mma8(float* c, const uint32_t* a, const uint32_t* b) {
    asm volatile("mma.sync.aligned.m16n8k8.row.col.f32.tf32.tf32.f32 "
        "{%0,%1,%2,%3}, {%4,%5,%6,%7}, {%8,%9}, {%0,%1,%2,%3};"
        : "+f"(c[0]), "+f"(c[1]), "+f"(c[2]), "+f"(c[3])
        : "r"(a[0]), "r"(a[1]), "r"(a[2]), "r"(a[3]), "r"(b[0]), "r"(b[1]));
}

// ======================= prep kernels =======================================
__global__ void cvt_x(const float* __restrict__ x) {
    size_t i = ((size_t)blockIdx.x * 256 + threadIdx.x) * 4;
    float4 v = *(const float4*)&x[i];
    v.x = f2tf(v.x); v.y = f2tf(v.y); v.z = f2tf(v.z); v.w = f2tf(v.w);
    *(float4*)&g_x[i] = v;
    if (blockIdx.x < 256) g_rowsum[blockIdx.x * 256 + threadIdx.x] = 0.f;
}

__global__ void transpose_w(const float* __restrict__ in, float* __restrict__ out,
                            int R, int C) {   // in[R][C] -> out[C][R], tf32-rounded
    __shared__ float tb[32][33];
    int bx = blockIdx.x * 32, by = blockIdx.y * 32;
    int x = bx + threadIdx.x;
    #pragma unroll
    for (int i = threadIdx.y; i < 32; i += 8)
        tb[i][threadIdx.x] = in[(size_t)(by + i) * C + x];
    __syncthreads();
    int x2 = by + threadIdx.x;
    #pragma unroll
    for (int i = threadIdx.y; i < 32; i += 8)
        out[(size_t)(bx + i) * R + x2] = f2tf(tb[threadIdx.x][i]);
}

__global__ void transpose_v() {   // g_v -> g_vt (tf32)
    __shared__ float tb[32][33];
    int bh = blockIdx.z;
    const float* in = g_v + (size_t)bh * T_ * HD;
    float* out = g_vt + (size_t)bh * HD * T_;
    int bx = blockIdx.x * 32, by = blockIdx.y * 32;
    int x = bx + threadIdx.x;
    #pragma unroll
    for (int i = threadIdx.y; i < 32; i += 8)
        tb[i][threadIdx.x] = in[(size_t)(by + i) * HD + x];
    __syncthreads();
    int x2 = by + threadIdx.x;
    #pragma unroll
    for (int i = threadIdx.y; i < 32; i += 8)
        out[(size_t)(bx + i) * T_ + x2] = f2tf(tb[threadIdx.x][i]);
}

// ======================= big projection GEMM ================================
// C[4096][N] = A[4096][1024] @ Bt[N][1024]^T. Tile 128x128, BK=16, 3 stages,
// one __syncthreads per k-iter. Operands pre-rounded tf32.
#define GBS 20
template <int MODE>
__global__ void __launch_bounds__(256, 2)
gemm_big(const float* __restrict__ A, const float* __restrict__ Bt,
         const float* __restrict__ bias, float* __restrict__ Cout) {
    extern __shared__ float sm[];
    float (*As)[128][GBS] = (float(*)[128][GBS])sm;
    float (*Bs)[128][GBS] = (float(*)[128][GBS])(sm + 3 * 128 * GBS);

    int tid = threadIdx.x, wid = tid >> 5, lane = tid & 31;
    int gr = lane >> 2, tq = lane & 3;
    int warpm = wid & 3, warpn = wid >> 2;
    int row0 = blockIdx.y * 128, col0 = blockIdx.x * 128;

    float acc[2][8][4];
    #pragma unroll
    for (int i = 0; i < 2; i++)
        #pragma unroll
        for (int j = 0; j < 8; j++)
            #pragma unroll
            for (int q = 0; q < 4; q++) acc[i][j][q] = 0.f;

    auto load_stage = [&](int c) {
        int s = c % 3;
        #pragma unroll
        for (int p = 0; p < 2; p++) {
            int idx = tid + p * 256;
            int r = idx >> 2, c4 = idx & 3;
            cpa16(s2u(&As[s][r][c4 * 4]), &A[(size_t)(row0 + r) * 1024 + c * 16 + c4 * 4]);
            cpa16(s2u(&Bs[s][r][c4 * 4]), &Bt[(size_t)(col0 + r) * 1024 + c * 16 + c4 * 4]);
        }
        cpcommit();
    };

    load_stage(0); load_stage(1);

    for (int c = 0; c < 64; c++) {
        int s = c % 3;
        if (c < 63) cpwait<1>(); else cpwait<0>();
        __syncthreads();

        #pragma unroll
        for (int k8 = 0; k8 < 16; k8 += 8) {
            uint32_t a[2][4];
            #pragma unroll
            for (int i = 0; i < 2; i++) {
                int r = warpm * 32 + i * 16 + gr;
                int cc = k8 + tq;
                a[i][0] = __float_as_uint(As[s][r][cc]);
                a[i][1] = __float_as_uint(As[s][r + 8][cc]);
                a[i][2] = __float_as_uint(As[s][r][cc + 4]);
                a[i][3] = __float_as_uint(As[s][r + 8][cc + 4]);
            }
            #pragma unroll
            for (int j = 0; j < 8; j++) {
                int nb = warpn * 64 + j * 8 + gr;
                uint32_t b[2];
                b[0] = __float_as_uint(Bs[s][nb][k8 + tq]);
                b[1] = __float_as_uint(Bs[s][nb][k8 + 4 + tq]);
                mma8(acc[0][j], a[0], b);
                mma8(acc[1][j], a[1], b);
            }
        }
        if (c + 2 < 64) load_stage(c + 2);
    }

    // ---- epilogue ----
    #pragma unroll
    for (int i = 0; i < 2; i++) {
        #pragma unroll
        for (int half = 0; half < 2; half++) {
            int m = row0 + warpm * 32 + i * 16 + gr + half * 8;
            #pragma unroll
            for (int j = 0; j < 8; j++) {
                int col = col0 + warpn * 64 + j * 8 + 2 * tq;
                float v0 = acc[i][j][half * 2 + 0] + __ldg(&bias[col]);
                float v1 = acc[i][j][half * 2 + 1] + __ldg(&bias[col + 1]);
                if (MODE == 1) {
                    *(float2*)&Cout[(size_t)m * 1024 + col] = make_float2(v0, v1);
                } else {
                    int which = col >> 10;
                    int d = col & 1023, h = d >> 6, dd = d & 63;
                    int b = m >> 11, t = m & 2047;
                    if (which != 2) { v0 = f2tf(v0); v1 = f2tf(v1); }  // q,k pre-round
                    float* dst = (which == 0) ? g_q : (which == 1) ? g_k : g_v;
                    *(float2*)&dst[((size_t)(b * NH + h) * T_ + t) * HD + dd] =
                        make_float2(v0, v1);
                }
            }
        }
    }
}

// ======================= scores + exp + rowsum ==============================
// Tile 128 q x 128 s, K=64 single shot. E = exp(score/8) -> wts; rowsums atomic.
__global__ void __launch_bounds__(256, 2) attn_scores(float* __restrict__ wts) {
    extern __shared__ float sm[];
    float* Qs = sm;               // [128][68]
    float* Ks = sm + 128 * 68;    // [128][68]

    int tid = threadIdx.x, wid = tid >> 5, lane = tid & 31;
    int gr = lane >> 2, tq = lane & 3;
    int warpm = wid & 3, warpn = wid >> 2;
    int s0 = blockIdx.x * 128, r0 = blockIdx.y * 128, bh = blockIdx.z;

    const float* qh = g_q + ((size_t)bh * T_ + r0) * HD;
    const float* kh = g_k + ((size_t)bh * T_ + s0) * HD;
    #pragma unroll
    for (int p = 0; p < 8; p++) {
        int idx = tid + p * 256;
        int r = idx >> 4, c4 = idx & 15;
        cpa16(s2u(&Qs[r * 68 + c4 * 4]), qh + (size_t)r * HD + c4 * 4);
        cpa16(s2u(&Ks[r * 68 + c4 * 4]), kh + (size_t)r * HD + c4 * 4);
    }
    cpcommit(); cpwait<0>();
    __syncthreads();

    float acc[2][8][4];
    #pragma unroll
    for (int i = 0; i < 2; i++)
        #pragma unroll
        for (int j = 0; j < 8; j++)
            #pragma unroll
            for (int q = 0; q < 4; q++) acc[i][j][q] = 0.f;

    #pragma unroll
    for (int k8 = 0; k8 < 64; k8 += 8) {
        uint32_t a[2][4];
        #pragma unroll
        for (int i = 0; i < 2; i++) {
            int r = warpm * 32 + i * 16 + gr;
            int cc = k8 + tq;
            a[i][0] = __float_as_uint(Qs[r * 68 + cc]);
            a[i][1] = __float_as_uint(Qs[(r + 8) * 68 + cc]);
            a[i][2] = __float_as_uint(Qs[r * 68 + cc + 4]);
            a[i][3] = __float_as_uint(Qs[(r + 8) * 68 + cc + 4]);
        }
        #pragma unroll
        for (int j = 0; j < 8; j++) {
            int nb = warpn * 64 + j * 8 + gr;
            uint32_t b[2];
            b[0] = __float_as_uint(Ks[nb * 68 + k8 + tq]);
            b[1] = __float_as_uint(Ks[nb * 68 + k8 + 4 + tq]);
            mma8(acc[0][j], a[0], b);
            mma8(acc[1][j], a[1], b);
        }
    }

    // exp + store + rowsum
    #pragma unroll
    for (int i = 0; i < 2; i++) {
        #pragma unroll
        for (int half = 0; half < 2; half++) {
            int r = r0 + warpm * 32 + i * 16 + gr + half * 8;
            float sum = 0.f;
            float* wr = wts + ((size_t)bh * T_ + r) * T_;
            #pragma unroll
            for (int j = 0; j < 8; j++) {
                int col = s0 + warpn * 64 + j * 8 + 2 * tq;
                float e0 = __expf(0.125f * acc[i][j][half * 2 + 0]);
                float e1 = __expf(0.125f * acc[i][j][half * 2 + 1]);
                sum += e0 + e1;
                *(float2*)&wr[col] = make_float2(e0, e1);
            }
            sum += __shfl_xor_sync(0xffffffffu, sum, 1);
            sum += __shfl_xor_sync(0xffffffffu, sum, 2);
            if (tq == 0) atomicAdd(&g_rowsum[(size_t)bh * T_ + r], sum);
        }
    }
}

// ======================= AV GEMM (normalize + writeback) ====================
// Tile 256 t x 64 dd, K=2048 (128 BK=16 chunks), 3-stage, 1 sync/iter.
// Warps 4(m) x 2(n): warp tile 64x32. E loaded by LDG one chunk ahead,
// normalized, written back (exact) + stored to smem (tf32).
#define AVS 20
__global__ void __launch_bounds__(256, 2) av_gemm(float* __restrict__ wts) {
    extern __shared__ float sm[];
    float (*Es)[256][AVS] = (float(*)[256][AVS])sm;
    float (*Vs)[64][AVS]  = (float(*)[64][AVS])(sm + 3 * 256 * AVS);
    float* inv = sm + 3 * 256 * AVS + 3 * 64 * AVS;

    int tid = threadIdx.x, wid = tid >> 5, lane = tid & 31;
    int gr = lane >> 2, tq = lane & 3;
    int warpm = wid & 3, warpn = wid >> 2;
    int r0 = blockIdx.x * 256, bh = blockIdx.y;

    inv[tid] = 1.f / g_rowsum[(size_t)bh * T_ + r0 + tid];

    float* wb = wts + ((size_t)bh * T_ + r0) * T_;
    const float* vtb = g_vt + (size_t)bh * HD * T_;

    // A: one row per thread, 16 cols per chunk (4 x float4)
    float4 pre[4];
    auto ldA = [&](int c) {
        #pragma unroll
        for (int u = 0; u < 4; u++)
            pre[u] = *(const float4*)&wb[(size_t)tid * T_ + c * 16 + u * 4];
    };
    auto stA = [&](int c) {   // needs inv[] visible
        int s = c % 3;
        float iv = inv[tid];
        #pragma unroll
        for (int u = 0; u < 4; u++) {
            float4 w = pre[u];
            w.x *= iv; w.y *= iv; w.z *= iv; w.w *= iv;
            *(float4*)&wb[(size_t)tid * T_ + c * 16 + u * 4] = w;
            w.x = f2tf(w.x); w.y = f2tf(w.y); w.z = f2tf(w.z); w.w = f2tf(w.w);
            *(float4*)&Es[s][tid][u * 4] = w;
        }
    };
    auto ldB = [&](int c) {
        int s = c % 3;
        int r = tid >> 2, c4 = tid & 3;
        cpa16(s2u(&Vs[s][r][c4 * 4]), vtb + (size_t)r * T_ + c * 16 + c4 * 4);
        cpcommit();
    };

    float acc[4][4][4];
    #pragma unroll
    for (int i = 0; i < 4; i++)
        #pragma unroll
        for (int j = 0; j < 4; j++)
            #pragma unroll
            for (int q = 0; q < 4; q++) acc[i][j][q] = 0.f;

    ldA(0); ldB(0); ldB(1);
    __syncthreads();            // inv visible
    stA(0);
    ldA(1); stA(1);
    ldA(2);

    for (int c = 0; c < 128; c++) {
        int s = c % 3;
        if (c < 127) cpwait<1>(); else cpwait<0>();
        __syncthreads();

        #pragma unroll
        for (int k8 = 0; k8 < 16; k8 += 8) {
            uint32_t a[4][4];
            #pragma unroll
            for (int i = 0; i < 4; i++) {
                int r = warpm * 64 + i * 16 + gr;
                int cc = k8 + tq;
                a[i][0] = __float_as_uint(Es[s][r][cc]);
                a[i][1] = __float_as_uint(Es[s][r + 8][cc]);
                a[i][2] = __float_as_uint(Es[s][r][cc + 4]);
                a[i][3] = __float_as_uint(Es[s][r + 8][cc + 4]);
            }
            #pragma unroll
            for (int j = 0; j < 4; j++) {
                int nb = warpn * 32 + j * 8 + gr;
                uint32_t b[2];
                b[0] = __float_as_uint(Vs[s][nb][k8 + tq]);
                b[1] = __float_as_uint(Vs[s][nb][k8 + 4 + tq]);
                #pragma unroll
                for (int i = 0; i < 4; i++) mma8(acc[i][j], a[i], b);
            }
        }
        if (c + 2 < 128) {
            stA(c + 2);
            if (c + 3 < 128) ldA(c + 3);
            ldB(c + 2);
        }
    }

    int b = bh >> 4, h = bh & 15;
    #pragma unroll
    for (int i = 0; i < 4; i++) {
        #pragma unroll
        for (int half = 0; half < 2; half++) {
            int t = r0 + warpm * 64 + i * 16 + gr + half * 8;
            float* orow = g_ao + (size_t)(b * T_ + t) * D_MODEL + h * HD;
            #pragma unroll
            for (int j = 0; j < 4; j++) {
                int dd = warpn * 32 + j * 8 + 2 * tq;
                *(float2*)&orow[dd] = make_float2(
                    f2tf(acc[i][j][half * 2 + 0]), f2tf(acc[i][j][half * 2 + 1]));
            }
        }
    }
}

// ===========================================================================
extern "C" void kernel_launch(void* const* d_in, const int* in_sizes, int n_in,
                              void* d_out, int out_size) {
    const float* x    = (const float*)d_in[0];
    const float* Wqkv = (const float*)d_in[1];
    const float* bqkv = (const float*)d_in[2];
    const float* Wo   = (const float*)d_in[3];
    const float* bo   = (const float*)d_in[4];

    float* y   = (float*)d_out;                         // [B,T,D]
    float* wts = (float*)d_out + (size_t)BT * D_MODEL;  // [B,H,T,T]

    const int GB_SMEM = 2 * 3 * 128 * GBS * 4;                      // 61440
    const int AV_SMEM = (3 * 256 * AVS + 3 * 64 * AVS + 256) * 4;   // 77824
    const int SC_SMEM = 2 * 128 * 68 * 4;                           // 69632
    cudaFuncSetAttribute(gemm_big<0>, cudaFuncAttributeMaxDynamicSharedMemorySize, GB_SMEM);
    cudaFuncSetAttribute(gemm_big<1>, cudaFuncAttributeMaxDynamicSharedMemorySize, GB_SMEM);
    cudaFuncSetAttribute(attn_scores, cudaFuncAttributeMaxDynamicSharedMemorySize, SC_SMEM);
    cudaFuncSetAttribute(av_gemm,     cudaFuncAttributeMaxDynamicSharedMemorySize, AV_SMEM);

    float *wt_p = nullptr, *wot_p = nullptr, *ao_p = nullptr, *x_p = nullptr;
    cudaGetSymbolAddress((void**)&wt_p,  g_wt);
    cudaGetSymbolAddress((void**)&wot_p, g_wot);
    cudaGetSymbolAddress((void**)&ao_p,  g_ao);
    cudaGetSymbolAddress((void**)&x_p,   g_x);

    cvt_x<<<BT * D_MODEL / 1024, 256>>>(x);   // also zeroes g_rowsum
    transpose_w<<<dim3(96, 32), dim3(32, 8)>>>(Wqkv, wt_p, 1024, 3072);
    transpose_w<<<dim3(32, 32), dim3(32, 8)>>>(Wo, wot_p, 1024, 1024);

    gemm_big<0><<<dim3(24, 32), 256, GB_SMEM>>>(x_p, wt_p, bqkv, nullptr);
    transpose_v<<<dim3(2, 64, 32), dim3(32, 8)>>>();

    attn_scores<<<dim3(16, 16, 32), 256, SC_SMEM>>>(wts);
    av_gemm<<<dim3(8, 32), 256, AV_SMEM>>>(wts);
    gemm_big<1><<<dim3(8, 32), 256, GB_SMEM>>>(ao_p, wot_p, bo, y);
}

// round 8
// speedup vs baseline: 1.1060x; 1.1060x over previous
#include <cuda_runtime.h>
#include <math.h>
#include <stdint.h>

#define D_MODEL 1024
#define NH      16
#define HD      64
#define B_      2
#define T_      2048
#define BT      4096
#define BH      32

// ------------------------- device scratch (no allocs) ----------------------
__device__ float g_x  [BT * D_MODEL];      // x, tf32-rounded
__device__ float g_q  [BH * T_ * HD];      // [bh][t][dd]   (tf32)
__device__ float g_k  [BH * T_ * HD];      // [bh][s][dd]   (tf32)
__device__ float g_v  [BH * T_ * HD];      // [bh][t][dd]   (exact)
__device__ float g_vt [BH * HD * T_];      // [bh][dd][t]   (tf32)
__device__ float g_ao [BT * D_MODEL];      // [b*t][D]      (tf32)
__device__ float g_wt [3 * D_MODEL * D_MODEL];   // Wqkv^T (tf32)
__device__ float g_wot[D_MODEL * D_MODEL];       // Wo^T   (tf32)
__device__ float g_rowsum[BH * T_];

// ------------------------------ helpers ------------------------------------
__device__ __forceinline__ uint32_t s2u(const void* p) {
    return (uint32_t)__cvta_generic_to_shared(p);
}
__device__ __forceinline__ void cpa16(uint32_t d, const void* g) {
    asm volatile("cp.async.cg.shared.global [%0], [%1], 16;" :: "r"(d), "l"(g));
}
__device__ __forceinline__ void cpcommit() { asm volatile("cp.async.commit_group;"); }
template <int N> __device__ __forceinline__ void cpwait() {
    asm volatile("cp.async.wait_group %0;" :: "n"(N));
}
__device__ __forceinline__ float f2tf(float f) {
    uint32_t r; asm("cvt.rna.tf32.f32 %0, %1;" : "=r"(r) : "f"(f));
    return __uint_as_float(r);
}
// m16n8k8 tf32 mma, fp32 accumulate (operands pre-rounded)
__device__ __forceinline__ void mma8(float* c, const uint32_t* a, const uint32_t* b) {
    asm volatile("mma.sync.aligned.m16n8k8.row.col.f32.tf32.tf32.f32 "
        "{%0,%1,%2,%3}, {%4,%5,%6,%7}, {%8,%9}, {%0,%1,%2,%3};"
        : "+f"(c[0]), "+f"(c[1]), "+f"(c[2]), "+f"(c[3])
        : "r"(a[0]), "r"(a[1]), "r"(a[2]), "r"(a[3]), "r"(b[0]), "r"(b[1]));
}

// ======================= prep kernels =======================================
__global__ void cvt_x(const float* __restrict__ x) {
    size_t i = ((size_t)blockIdx.x * 256 + threadIdx.x) * 4;
    float4 v = *(const float4*)&x[i];
    v.x = f2tf(v.x); v.y = f2tf(v.y); v.z = f2tf(v.z); v.w = f2tf(v.w);
    *(float4*)&g_x[i] = v;
    if (blockIdx.x < 256) g_rowsum[blockIdx.x * 256 + threadIdx.x] = 0.f;
}

__global__ void transpose_w(const float* __restrict__ in, float* __restrict__ out,
                            int R, int C) {
    __shared__ float tb[32][33];
    int bx = blockIdx.x * 32, by = blockIdx.y * 32;
    int x = bx + threadIdx.x;
    #pragma unroll
    for (int i = threadIdx.y; i < 32; i += 8)
        tb[i][threadIdx.x] = in[(size_t)(by + i) * C + x];
    __syncthreads();
    int x2 = by + threadIdx.x;
    #pragma unroll
    for (int i = threadIdx.y; i < 32; i += 8)
        out[(size_t)(bx + i) * R + x2] = f2tf(tb[threadIdx.x][i]);
}

__global__ void transpose_v() {
    __shared__ float tb[32][33];
    int bh = blockIdx.z;
    const float* in = g_v + (size_t)bh * T_ * HD;
    float* out = g_vt + (size_t)bh * HD * T_;
    int bx = blockIdx.x * 32, by = blockIdx.y * 32;
    int x = bx + threadIdx.x;
    #pragma unroll
    for (int i = threadIdx.y; i < 32; i += 8)
        tb[i][threadIdx.x] = in[(size_t)(by + i) * HD + x];
    __syncthreads();
    int x2 = by + threadIdx.x;
    #pragma unroll
    for (int i = threadIdx.y; i < 32; i += 8)
        out[(size_t)(bx + i) * T_ + x2] = f2tf(tb[threadIdx.x][i]);
}

// ======================= big projection GEMM (unchanged R6) =================
#define GBS 20
template <int MODE>
__global__ void __launch_bounds__(256, 2)
gemm_big(const float* __restrict__ A, const float* __restrict__ Bt,
         const float* __restrict__ bias, float* __restrict__ Cout) {
    extern __shared__ float sm[];
    float (*As)[128][GBS] = (float(*)[128][GBS])sm;
    float (*Bs)[128][GBS] = (float(*)[128][GBS])(sm + 3 * 128 * GBS);

    int tid = threadIdx.x, wid = tid >> 5, lane = tid & 31;
    int gr = lane >> 2, tq = lane & 3;
    int warpm = wid & 3, warpn = wid >> 2;
    int row0 = blockIdx.y * 128, col0 = blockIdx.x * 128;

    float acc[2][8][4];
    #pragma unroll
    for (int i = 0; i < 2; i++)
        #pragma unroll
        for (int j = 0; j < 8; j++)
            #pragma unroll
            for (int q = 0; q < 4; q++) acc[i][j][q] = 0.f;

    auto load_stage = [&](int c) {
        int s = c % 3;
        #pragma unroll
        for (int p = 0; p < 2; p++) {
            int idx = tid + p * 256;
            int r = idx >> 2, c4 = idx & 3;
            cpa16(s2u(&As[s][r][c4 * 4]), &A[(size_t)(row0 + r) * 1024 + c * 16 + c4 * 4]);
            cpa16(s2u(&Bs[s][r][c4 * 4]), &Bt[(size_t)(col0 + r) * 1024 + c * 16 + c4 * 4]);
        }
        cpcommit();
    };

    load_stage(0); load_stage(1);

    for (int c = 0; c < 64; c++) {
        int s = c % 3;
        if (c < 63) cpwait<1>(); else cpwait<0>();
        __syncthreads();

        #pragma unroll
        for (int k8 = 0; k8 < 16; k8 += 8) {
            uint32_t a[2][4];
            #pragma unroll
            for (int i = 0; i < 2; i++) {
                int r = warpm * 32 + i * 16 + gr;
                int cc = k8 + tq;
                a[i][0] = __float_as_uint(As[s][r][cc]);
                a[i][1] = __float_as_uint(As[s][r + 8][cc]);
                a[i][2] = __float_as_uint(As[s][r][cc + 4]);
                a[i][3] = __float_as_uint(As[s][r + 8][cc + 4]);
            }
            #pragma unroll
            for (int j = 0; j < 8; j++) {
                int nb = warpn * 64 + j * 8 + gr;
                uint32_t b[2];
                b[0] = __float_as_uint(Bs[s][nb][k8 + tq]);
                b[1] = __float_as_uint(Bs[s][nb][k8 + 4 + tq]);
                mma8(acc[0][j], a[0], b);
                mma8(acc[1][j], a[1], b);
            }
        }
        if (c + 2 < 64) load_stage(c + 2);
    }

    #pragma unroll
    for (int i = 0; i < 2; i++) {
        #pragma unroll
        for (int half = 0; half < 2; half++) {
            int m = row0 + warpm * 32 + i * 16 + gr + half * 8;
            #pragma unroll
            for (int j = 0; j < 8; j++) {
                int col = col0 + warpn * 64 + j * 8 + 2 * tq;
                float v0 = acc[i][j][half * 2 + 0] + __ldg(&bias[col]);
                float v1 = acc[i][j][half * 2 + 1] + __ldg(&bias[col + 1]);
                if (MODE == 1) {
                    *(float2*)&Cout[(size_t)m * 1024 + col] = make_float2(v0, v1);
                } else {
                    int which = col >> 10;
                    int d = col & 1023, h = d >> 6, dd = d & 63;
                    int b = m >> 11, t = m & 2047;
                    if (which != 2) { v0 = f2tf(v0); v1 = f2tf(v1); }
                    float* dst = (which == 0) ? g_q : (which == 1) ? g_k : g_v;
                    *(float2*)&dst[((size_t)(b * NH + h) * T_ + t) * HD + dd] =
                        make_float2(v0, v1);
                }
            }
        }
    }
}

// ======================= kernel A: rowsums only =============================
// Per CTA: (bh, 128 q-rows) x all 2048 keys in 16 chunks (2-stage).
// Accumulates sum(exp(score/8)) per row in registers; atomicAdd at end.
__global__ void __launch_bounds__(256, 2) attn_rowsum() {
    extern __shared__ float sm[];
    float* Qs = sm;                 // [128][68]
    float* Ks = sm + 128 * 68;      // [2][128][68]

    int tid = threadIdx.x, wid = tid >> 5, lane = tid & 31;
    int gr = lane >> 2, tq = lane & 3;
    int warpm = wid & 3, warpn = wid >> 2;
    int r0 = blockIdx.x * 128, bh = blockIdx.y;

    const float* qh = g_q + ((size_t)bh * T_ + r0) * HD;
    const float* kh = g_k + (size_t)bh * T_ * HD;

    auto loadK = [&](int c) {
        float* dst = Ks + (size_t)(c & 1) * 128 * 68;
        #pragma unroll
        for (int p = 0; p < 8; p++) {
            int idx = tid + p * 256;
            int r = idx >> 4, c4 = idx & 15;
            cpa16(s2u(&dst[r * 68 + c4 * 4]), kh + (size_t)(c * 128 + r) * HD + c4 * 4);
        }
        cpcommit();
    };

    // prologue: Q + K[0] in one group, K[1] second group
    #pragma unroll
    for (int p = 0; p < 8; p++) {
        int idx = tid + p * 256;
        int r = idx >> 4, c4 = idx & 15;
        cpa16(s2u(&Qs[r * 68 + c4 * 4]), qh + (size_t)r * HD + c4 * 4);
    }
    {
        float* dst = Ks;
        #pragma unroll
        for (int p = 0; p < 8; p++) {
            int idx = tid + p * 256;
            int r = idx >> 4, c4 = idx & 15;
            cpa16(s2u(&dst[r * 68 + c4 * 4]), kh + (size_t)r * HD + c4 * 4);
        }
    }
    cpcommit();
    loadK(1);

    float sums[2][2] = {{0.f, 0.f}, {0.f, 0.f}};

    for (int c = 0; c < 16; c++) {
        if (c < 15) cpwait<1>(); else cpwait<0>();
        __syncthreads();
        const float* Kb = Ks + (size_t)(c & 1) * 128 * 68;

        float acc[2][8][4];
        #pragma unroll
        for (int i = 0; i < 2; i++)
            #pragma unroll
            for (int j = 0; j < 8; j++)
                #pragma unroll
                for (int q = 0; q < 4; q++) acc[i][j][q] = 0.f;

        #pragma unroll
        for (int k8 = 0; k8 < 64; k8 += 8) {
            uint32_t a[2][4];
            #pragma unroll
            for (int i = 0; i < 2; i++) {
                int r = warpm * 32 + i * 16 + gr;
                int cc = k8 + tq;
                a[i][0] = __float_as_uint(Qs[r * 68 + cc]);
                a[i][1] = __float_as_uint(Qs[(r + 8) * 68 + cc]);
                a[i][2] = __float_as_uint(Qs[r * 68 + cc + 4]);
                a[i][3] = __float_as_uint(Qs[(r + 8) * 68 + cc + 4]);
            }
            #pragma unroll
            for (int j = 0; j < 8; j++) {
                int nb = warpn * 64 + j * 8 + gr;
                uint32_t b[2];
                b[0] = __float_as_uint(Kb[nb * 68 + k8 + tq]);
                b[1] = __float_as_uint(Kb[nb * 68 + k8 + 4 + tq]);
                mma8(acc[0][j], a[0], b);
                mma8(acc[1][j], a[1], b);
            }
        }

        #pragma unroll
        for (int i = 0; i < 2; i++)
            #pragma unroll
            for (int half = 0; half < 2; half++) {
                float s = 0.f;
                #pragma unroll
                for (int j = 0; j < 8; j++) {
                    s += __expf(0.125f * acc[i][j][half * 2 + 0]);
                    s += __expf(0.125f * acc[i][j][half * 2 + 1]);
                }
                sums[i][half] += s;
            }

        __syncthreads();                       // buf (c&1) free
        if (c + 2 < 16) loadK(c + 2);
    }

    #pragma unroll
    for (int i = 0; i < 2; i++)
        #pragma unroll
        for (int half = 0; half < 2; half++) {
            float s = sums[i][half];
            s += __shfl_xor_sync(0xffffffffu, s, 1);
            s += __shfl_xor_sync(0xffffffffu, s, 2);
            if (tq == 0) {
                int r = r0 + warpm * 32 + i * 16 + gr + half * 8;
                atomicAdd(&g_rowsum[(size_t)bh * T_ + r], s);
            }
        }
}

// ======================= kernel B: fused W-write + O accumulate =============
// Per CTA: (bh, 128 q-rows). For each of 16 s-chunks (128 keys):
//   S = Q K^T (mma), w = exp(S/8)*inv  -> write W to gmem, store tf32 to Es,
//   O += Es @ V  (mma, B = Vt chunk).
// Smem (floats): Qs 128x68 | Ks 2x128x68 | Es 128x130 | Vs 64x132 | inv 128
#define FB_QS   0
#define FB_KS   (128 * 68)
#define FB_ES   (FB_KS + 2 * 128 * 68)
#define FB_VS   (FB_ES + 128 * 130)
#define FB_INV  (FB_VS + 64 * 132)
#define FB_FLTS (FB_INV + 128)

__global__ void __launch_bounds__(256, 1) attn_fused(float* __restrict__ wts) {
    extern __shared__ float sm[];
    float* Qs  = sm + FB_QS;
    float* Ks  = sm + FB_KS;
    float* Es  = sm + FB_ES;
    float* Vs  = sm + FB_VS;
    float* inv = sm + FB_INV;

    int tid = threadIdx.x, wid = tid >> 5, lane = tid & 31;
    int gr = lane >> 2, tq = lane & 3;
    int warpm = wid & 3, warpn = wid >> 2;
    int r0 = blockIdx.x * 128, bh = blockIdx.y;

    const float* qh  = g_q  + ((size_t)bh * T_ + r0) * HD;
    const float* kh  = g_k  + (size_t)bh * T_ * HD;
    const float* vtb = g_vt + (size_t)bh * HD * T_;
    float* wbase = wts + ((size_t)bh * T_ + r0) * T_;

    if (tid < 128) inv[tid] = 1.f / g_rowsum[(size_t)bh * T_ + r0 + tid];

    auto loadK = [&](int c) {
        float* dst = Ks + (size_t)(c & 1) * 128 * 68;
        #pragma unroll
        for (int p = 0; p < 8; p++) {
            int idx = tid + p * 256;
            int r = idx >> 4, c4 = idx & 15;
            cpa16(s2u(&dst[r * 68 + c4 * 4]), kh + (size_t)(c * 128 + r) * HD + c4 * 4);
        }
        cpcommit();
    };
    auto loadV = [&](int c) {
        #pragma unroll
        for (int p = 0; p < 8; p++) {
            int idx = tid + p * 256;
            int r = idx >> 5, c4 = idx & 31;
            cpa16(s2u(&Vs[r * 132 + c4 * 4]), vtb + (size_t)r * T_ + c * 128 + c4 * 4);
        }
        cpcommit();
    };

    // prologue: Q + K[0] (one group)
    #pragma unroll
    for (int p = 0; p < 8; p++) {
        int idx = tid + p * 256;
        int r = idx >> 4, c4 = idx & 15;
        cpa16(s2u(&Qs[r * 68 + c4 * 4]), qh + (size_t)r * HD + c4 * 4);
    }
    {
        float* dst = Ks;
        #pragma unroll
        for (int p = 0; p < 8; p++) {
            int idx = tid + p * 256;
            int r = idx >> 4, c4 = idx & 15;
            cpa16(s2u(&dst[r * 68 + c4 * 4]), kh + (size_t)r * HD + c4 * 4);
        }
    }
    cpcommit();

    float acco[2][4][4];
    #pragma unroll
    for (int i = 0; i < 2; i++)
        #pragma unroll
        for (int j = 0; j < 4; j++)
            #pragma unroll
            for (int q = 0; q < 4; q++) acco[i][j][q] = 0.f;

    for (int c = 0; c < 16; c++) {
        cpwait<0>();                 // K[c] (and any prior) arrived
        __syncthreads();             // Ks visible; Es/Vs free (prev EV done); inv ready
        loadV(c);                    // group V
        if (c < 15) loadK(c + 1);    // group K (other buffer)

        const float* Kb = Ks + (size_t)(c & 1) * 128 * 68;

        // ---- QK^T ----
        float acc[2][8][4];
        #pragma unroll
        for (int i = 0; i < 2; i++)
            #pragma unroll
            for (int j = 0; j < 8; j++)
                #pragma unroll
                for (int q = 0; q < 4; q++) acc[i][j][q] = 0.f;

        #pragma unroll
        for (int k8 = 0; k8 < 64; k8 += 8) {
            uint32_t a[2][4];
            #pragma unroll
            for (int i = 0; i < 2; i++) {
                int r = warpm * 32 + i * 16 + gr;
                int cc = k8 + tq;
                a[i][0] = __float_as_uint(Qs[r * 68 + cc]);
                a[i][1] = __float_as_uint(Qs[(r + 8) * 68 + cc]);
                a[i][2] = __float_as_uint(Qs[r * 68 + cc + 4]);
                a[i][3] = __float_as_uint(Qs[(r + 8) * 68 + cc + 4]);
            }
            #pragma unroll
            for (int j = 0; j < 8; j++) {
                int nb = warpn * 64 + j * 8 + gr;
                uint32_t b[2];
                b[0] = __float_as_uint(Kb[nb * 68 + k8 + tq]);
                b[1] = __float_as_uint(Kb[nb * 68 + k8 + 4 + tq]);
                mma8(acc[0][j], a[0], b);
                mma8(acc[1][j], a[1], b);
            }
        }

        // ---- w = exp*inv: write W gmem + store tf32 to Es ----
        #pragma unroll
        for (int i = 0; i < 2; i++) {
            #pragma unroll
            for (int half = 0; half < 2; half++) {
                int lr = warpm * 32 + i * 16 + gr + half * 8;
                float iv = inv[lr];
                float* wr = wbase + (size_t)lr * T_ + c * 128;
                #pragma unroll
                for (int j = 0; j < 8; j++) {
                    int col = warpn * 64 + j * 8 + 2 * tq;
                    float w0 = __expf(0.125f * acc[i][j][half * 2 + 0]) * iv;
                    float w1 = __expf(0.125f * acc[i][j][half * 2 + 1]) * iv;
                    *(float2*)&wr[col] = make_float2(w0, w1);
                    *(float2*)&Es[lr * 130 + col] = make_float2(f2tf(w0), f2tf(w1));
                }
            }
        }

        if (c < 15) cpwait<1>(); else cpwait<0>();   // V[c] arrived
        __syncthreads();                              // Es + Vs visible

        // ---- O += Es @ V ----
        #pragma unroll
        for (int k8 = 0; k8 < 128; k8 += 8) {
            uint32_t a[2][4];
            #pragma unroll
            for (int i = 0; i < 2; i++) {
                int r = warpm * 32 + i * 16 + gr;
                int cc = k8 + tq;
                a[i][0] = __float_as_uint(Es[r * 130 + cc]);
                a[i][1] = __float_as_uint(Es[(r + 8) * 130 + cc]);
                a[i][2] = __float_as_uint(Es[r * 130 + cc + 4]);
                a[i][3] = __float_as_uint(Es[(r + 8) * 130 + cc + 4]);
            }
            #pragma unroll
            for (int j = 0; j < 4; j++) {
                int nb = warpn * 32 + j * 8 + gr;
                uint32_t b[2];
                b[0] = __float_as_uint(Vs[nb * 132 + k8 + tq]);
                b[1] = __float_as_uint(Vs[nb * 132 + k8 + 4 + tq]);
                mma8(acco[0][j], a[0], b);
                mma8(acco[1][j], a[1], b);
            }
        }
    }

    // ---- epilogue: O -> g_ao (tf32) ----
    int b = bh >> 4, h = bh & 15;
    #pragma unroll
    for (int i = 0; i < 2; i++) {
        #pragma unroll
        for (int half = 0; half < 2; half++) {
            int t = r0 + warpm * 32 + i * 16 + gr + half * 8;
            float* orow = g_ao + (size_t)(b * T_ + t) * D_MODEL + h * HD;
            #pragma unroll
            for (int j = 0; j < 4; j++) {
                int dd = warpn * 32 + j * 8 + 2 * tq;
                *(float2*)&orow[dd] = make_float2(
                    f2tf(acco[i][j][half * 2 + 0]), f2tf(acco[i][j][half * 2 + 1]));
            }
        }
    }
}

// ===========================================================================
extern "C" void kernel_launch(void* const* d_in, const int* in_sizes, int n_in,
                              void* d_out, int out_size) {
    const float* x    = (const float*)d_in[0];
    const float* Wqkv = (const float*)d_in[1];
    const float* bqkv = (const float*)d_in[2];
    const float* Wo   = (const float*)d_in[3];
    const float* bo   = (const float*)d_in[4];

    float* y   = (float*)d_out;                         // [B,T,D]
    float* wts = (float*)d_out + (size_t)BT * D_MODEL;  // [B,H,T,T]

    const int GB_SMEM = 2 * 3 * 128 * GBS * 4;          // 61440
    const int RS_SMEM = 3 * 128 * 68 * 4;               // 104448
    const int FB_SMEM = FB_FLTS * 4;                    // 205312
    cudaFuncSetAttribute(gemm_big<0>, cudaFuncAttributeMaxDynamicSharedMemorySize, GB_SMEM);
    cudaFuncSetAttribute(gemm_big<1>, cudaFuncAttributeMaxDynamicSharedMemorySize, GB_SMEM);
    cudaFuncSetAttribute(attn_rowsum, cudaFuncAttributeMaxDynamicSharedMemorySize, RS_SMEM);
    cudaFuncSetAttribute(attn_fused,  cudaFuncAttributeMaxDynamicSharedMemorySize, FB_SMEM);

    float *wt_p = nullptr, *wot_p = nullptr, *ao_p = nullptr, *x_p = nullptr;
    cudaGetSymbolAddress((void**)&wt_p,  g_wt);
    cudaGetSymbolAddress((void**)&wot_p, g_wot);
    cudaGetSymbolAddress((void**)&ao_p,  g_ao);
    cudaGetSymbolAddress((void**)&x_p,   g_x);

    cvt_x<<<BT * D_MODEL / 1024, 256>>>(x);   // also zeroes g_rowsum
    transpose_w<<<dim3(96, 32), dim3(32, 8)>>>(Wqkv, wt_p, 1024, 3072);
    transpose_w<<<dim3(32, 32), dim3(32, 8)>>>(Wo, wot_p, 1024, 1024);

    gemm_big<0><<<dim3(24, 32), 256, GB_SMEM>>>(x_p, wt_p, bqkv, nullptr);
    transpose_v<<<dim3(2, 64, 32), dim3(32, 8)>>>();

    attn_rowsum<<<dim3(16, 32), 256, RS_SMEM>>>();
    attn_fused<<<dim3(16, 32), 256, FB_SMEM>>>(wts);

    gemm_big<1><<<dim3(8, 32), 256, GB_SMEM>>>(ao_p, wot_p, bo, y);
}

// round 10
// speedup vs baseline: 1.2440x; 1.1248x over previous
#include <cuda_runtime.h>
#include <math.h>
#include <stdint.h>

#define D_MODEL 1024
#define NH      16
#define HD      64
#define B_      2
#define T_      2048
#define BT      4096
#define BH      32

// ------------------------- device scratch (no allocs) ----------------------
__device__ float g_x  [BT * D_MODEL];      // x, tf32-rounded
__device__ float g_q  [BH * T_ * HD];      // [bh][t][dd]   (tf32)
__device__ float g_k  [BH * T_ * HD];      // [bh][s][dd]   (tf32)
__device__ float g_v  [BH * T_ * HD];      // [bh][t][dd]   (exact)
__device__ float g_vt [BH * HD * T_];      // [bh][dd][t]   (tf32)
__device__ float g_ao [BT * D_MODEL];      // [b*t][D]      (tf32)
__device__ float g_wt [3 * D_MODEL * D_MODEL];   // Wqkv^T (tf32)
__device__ float g_wot[D_MODEL * D_MODEL];       // Wo^T   (tf32)
__device__ float g_rowsum[BH * T_];

// ------------------------------ helpers ------------------------------------
__device__ __forceinline__ uint32_t s2u(const void* p) {
    return (uint32_t)__cvta_generic_to_shared(p);
}
__device__ __forceinline__ void cpa16(uint32_t d, const void* g) {
    asm volatile("cp.async.cg.shared.global [%0], [%1], 16;" :: "r"(d), "l"(g));
}
__device__ __forceinline__ void cpcommit() { asm volatile("cp.async.commit_group;"); }
template <int N> __device__ __forceinline__ void cpwait() {
    asm volatile("cp.async.wait_group %0;" :: "n"(N));
}
__device__ __forceinline__ float f2tf(float f) {
    uint32_t r; asm("cvt.rna.tf32.f32 %0, %1;" : "=r"(r) : "f"(f));
    return __uint_as_float(r);
}
// m16n8k8 tf32 mma, fp32 accumulate (operands pre-rounded or raw-truncated)
__device__ __forceinline__ void mma8(float* c, const uint32_t* a, const uint32_t* b) {
    asm volatile("mma.sync.aligned.m16n8k8.row.col.f32.tf32.tf32.f32 "
        "{%0,%1,%2,%3}, {%4,%5,%6,%7}, {%8,%9}, {%0,%1,%2,%3};"
        : "+f"(c[0]), "+f"(c[1]), "+f"(c[2]), "+f"(c[3])
        : "r"(a[0]), "r"(a[1]), "r"(a[2]), "r"(a[3]), "r"(b[0]), "r"(b[1]));
}

// ======================= prep kernels =======================================
__global__ void cvt_x(const float* __restrict__ x) {
    size_t i = ((size_t)blockIdx.x * 256 + threadIdx.x) * 4;
    float4 v = *(const float4*)&x[i];
    v.x = f2tf(v.x); v.y = f2tf(v.y); v.z = f2tf(v.z); v.w = f2tf(v.w);
    *(float4*)&g_x[i] = v;
    if (blockIdx.x < 256) g_rowsum[blockIdx.x * 256 + threadIdx.x] = 0.f;
}

__global__ void transpose_w(const float* __restrict__ in, float* __restrict__ out,
                            int R, int C) {
    __shared__ float tb[32][33];
    int bx = blockIdx.x * 32, by = blockIdx.y * 32;
    int x = bx + threadIdx.x;
    #pragma unroll
    for (int i = threadIdx.y; i < 32; i += 8)
        tb[i][threadIdx.x] = in[(size_t)(by + i) * C + x];
    __syncthreads();
    int x2 = by + threadIdx.x;
    #pragma unroll
    for (int i = threadIdx.y; i < 32; i += 8)
        out[(size_t)(bx + i) * R + x2] = f2tf(tb[threadIdx.x][i]);
}

__global__ void transpose_v() {
    __shared__ float tb[32][33];
    int bh = blockIdx.z;
    const float* in = g_v + (size_t)bh * T_ * HD;
    float* out = g_vt + (size_t)bh * HD * T_;
    int bx = blockIdx.x * 32, by = blockIdx.y * 32;
    int x = bx + threadIdx.x;
    #pragma unroll
    for (int i = threadIdx.y; i < 32; i += 8)
        tb[i][threadIdx.x] = in[(size_t)(by + i) * HD + x];
    __syncthreads();
    int x2 = by + threadIdx.x;
    #pragma unroll
    for (int i = threadIdx.y; i < 32; i += 8)
        out[(size_t)(bx + i) * T_ + x2] = f2tf(tb[threadIdx.x][i]);
}

// ======================= big projection GEMM (BK=32, 3-stage) ===============
#define GBS 36
template <int MODE>
__global__ void __launch_bounds__(256, 2)
gemm_big(const float* __restrict__ A, const float* __restrict__ Bt,
         const float* __restrict__ bias, float* __restrict__ Cout) {
    extern __shared__ float sm[];
    float (*As)[128][GBS] = (float(*)[128][GBS])sm;
    float (*Bs)[128][GBS] = (float(*)[128][GBS])(sm + 3 * 128 * GBS);

    int tid = threadIdx.x, wid = tid >> 5, lane = tid & 31;
    int gr = lane >> 2, tq = lane & 3;
    int warpm = wid & 3, warpn = wid >> 2;
    int row0 = blockIdx.y * 128, col0 = blockIdx.x * 128;

    float acc[2][8][4];
    #pragma unroll
    for (int i = 0; i < 2; i++)
        #pragma unroll
        for (int j = 0; j < 8; j++)
            #pragma unroll
            for (int q = 0; q < 4; q++) acc[i][j][q] = 0.f;

    auto load_stage = [&](int c) {
        int s = c % 3;
        #pragma unroll
        for (int p = 0; p < 4; p++) {
            int idx = tid + p * 256;
            int r = idx >> 3, c16 = idx & 7;
            cpa16(s2u(&As[s][r][c16 * 4]), &A[(size_t)(row0 + r) * 1024 + c * 32 + c16 * 4]);
            cpa16(s2u(&Bs[s][r][c16 * 4]), &Bt[(size_t)(col0 + r) * 1024 + c * 32 + c16 * 4]);
        }
        cpcommit();
    };

    load_stage(0); load_stage(1);

    for (int c = 0; c < 32; c++) {
        int s = c % 3;
        if (c < 31) cpwait<1>(); else cpwait<0>();
        __syncthreads();

        #pragma unroll
        for (int k8 = 0; k8 < 32; k8 += 8) {
            uint32_t a[2][4];
            #pragma unroll
            for (int i = 0; i < 2; i++) {
                int r = warpm * 32 + i * 16 + gr;
                int cc = k8 + tq;
                a[i][0] = __float_as_uint(As[s][r][cc]);
                a[i][1] = __float_as_uint(As[s][r + 8][cc]);
                a[i][2] = __float_as_uint(As[s][r][cc + 4]);
                a[i][3] = __float_as_uint(As[s][r + 8][cc + 4]);
            }
            #pragma unroll
            for (int j = 0; j < 8; j++) {
                int nb = warpn * 64 + j * 8 + gr;
                uint32_t b[2];
                b[0] = __float_as_uint(Bs[s][nb][k8 + tq]);
                b[1] = __float_as_uint(Bs[s][nb][k8 + 4 + tq]);
                mma8(acc[0][j], a[0], b);
                mma8(acc[1][j], a[1], b);
            }
        }
        if (c + 2 < 32) load_stage(c + 2);
    }

    #pragma unroll
    for (int i = 0; i < 2; i++) {
        #pragma unroll
        for (int half = 0; half < 2; half++) {
            int m = row0 + warpm * 32 + i * 16 + gr + half * 8;
            #pragma unroll
            for (int j = 0; j < 8; j++) {
                int col = col0 + warpn * 64 + j * 8 + 2 * tq;
                float v0 = acc[i][j][half * 2 + 0] + __ldg(&bias[col]);
                float v1 = acc[i][j][half * 2 + 1] + __ldg(&bias[col + 1]);
                if (MODE == 1) {
                    *(float2*)&Cout[(size_t)m * 1024 + col] = make_float2(v0, v1);
                } else {
                    int which = col >> 10;
                    int d = col & 1023, h = d >> 6, dd = d & 63;
                    int b = m >> 11, t = m & 2047;
                    if (which != 2) { v0 = f2tf(v0); v1 = f2tf(v1); }
                    float* dst = (which == 0) ? g_q : (which == 1) ? g_k : g_v;
                    *(float2*)&dst[((size_t)(b * NH + h) * T_ + t) * HD + dd] =
                        make_float2(v0, v1);
                }
            }
        }
    }
}

// ======================= kernel A: rowsums only =============================
__global__ void __launch_bounds__(256, 2) attn_rowsum() {
    extern __shared__ float sm[];
    float* Qs = sm;                 // [128][68]
    float* Ks = sm + 128 * 68;      // [2][128][68]

    int tid = threadIdx.x, wid = tid >> 5, lane = tid & 31;
    int gr = lane >> 2, tq = lane & 3;
    int warpm = wid & 3, warpn = wid >> 2;
    int r0 = blockIdx.x * 128, bh = blockIdx.y;

    const float* qh = g_q + ((size_t)bh * T_ + r0) * HD;
    const float* kh = g_k + (size_t)bh * T_ * HD;

    auto loadK = [&](int c) {
        float* dst = Ks + (size_t)(c & 1) * 128 * 68;
        #pragma unroll
        for (int p = 0; p < 8; p++) {
            int idx = tid + p * 256;
            int r = idx >> 4, c4 = idx & 15;
            cpa16(s2u(&dst[r * 68 + c4 * 4]), kh + (size_t)(c * 128 + r) * HD + c4 * 4);
        }
        cpcommit();
    };

    #pragma unroll
    for (int p = 0; p < 8; p++) {
        int idx = tid + p * 256;
        int r = idx >> 4, c4 = idx & 15;
        cpa16(s2u(&Qs[r * 68 + c4 * 4]), qh + (size_t)r * HD + c4 * 4);
    }
    {
        float* dst = Ks;
        #pragma unroll
        for (int p = 0; p < 8; p++) {
            int idx = tid + p * 256;
            int r = idx >> 4, c4 = idx & 15;
            cpa16(s2u(&dst[r * 68 + c4 * 4]), kh + (size_t)r * HD + c4 * 4);
        }
    }
    cpcommit();
    loadK(1);

    float sums[2][2] = {{0.f, 0.f}, {0.f, 0.f}};

    for (int c = 0; c < 16; c++) {
        if (c < 15) cpwait<1>(); else cpwait<0>();
        __syncthreads();
        const float* Kb = Ks + (size_t)(c & 1) * 128 * 68;

        float acc[2][8][4];
        #pragma unroll
        for (int i = 0; i < 2; i++)
            #pragma unroll
            for (int j = 0; j < 8; j++)
                #pragma unroll
                for (int q = 0; q < 4; q++) acc[i][j][q] = 0.f;

        #pragma unroll
        for (int k8 = 0; k8 < 64; k8 += 8) {
            uint32_t a[2][4];
            #pragma unroll
            for (int i = 0; i < 2; i++) {
                int r = warpm * 32 + i * 16 + gr;
                int cc = k8 + tq;
                a[i][0] = __float_as_uint(Qs[r * 68 + cc]);
                a[i][1] = __float_as_uint(Qs[(r + 8) * 68 + cc]);
                a[i][2] = __float_as_uint(Qs[r * 68 + cc + 4]);
                a[i][3] = __float_as_uint(Qs[(r + 8) * 68 + cc + 4]);
            }
            #pragma unroll
            for (int j = 0; j < 8; j++) {
                int nb = warpn * 64 + j * 8 + gr;
                uint32_t b[2];
                b[0] = __float_as_uint(Kb[nb * 68 + k8 + tq]);
                b[1] = __float_as_uint(Kb[nb * 68 + k8 + 4 + tq]);
                mma8(acc[0][j], a[0], b);
                mma8(acc[1][j], a[1], b);
            }
        }

        #pragma unroll
        for (int i = 0; i < 2; i++)
            #pragma unroll
            for (int half = 0; half < 2; half++) {
                float s = 0.f;
                #pragma unroll
                for (int j = 0; j < 8; j++) {
                    s += __expf(0.125f * acc[i][j][half * 2 + 0]);
                    s += __expf(0.125f * acc[i][j][half * 2 + 1]);
                }
                sums[i][half] += s;
            }

        __syncthreads();
        if (c + 2 < 16) loadK(c + 2);
    }

    #pragma unroll
    for (int i = 0; i < 2; i++)
        #pragma unroll
        for (int half = 0; half < 2; half++) {
            float s = sums[i][half];
            s += __shfl_xor_sync(0xffffffffu, s, 1);
            s += __shfl_xor_sync(0xffffffffu, s, 2);
            if (tq == 0) {
                int r = r0 + warpm * 32 + i * 16 + gr + half * 8;
                atomicAdd(&g_rowsum[(size_t)bh * T_ + r], s);
            }
        }
}

// ======================= kernel B: fused W-write + O accumulate =============
// Es stride 132 floats (528 B, 16B-aligned rows) for float4 access.
#define ESS 132
#define FB_QS   0
#define FB_KS   (128 * 68)
#define FB_ES   (FB_KS + 2 * 128 * 68)
#define FB_VS   (FB_ES + 128 * ESS)
#define FB_INV  (FB_VS + 64 * 132)
#define FB_FLTS (FB_INV + 128)

__global__ void __launch_bounds__(256, 1) attn_fused(float* __restrict__ wts) {
    extern __shared__ float sm[];
    float* Qs  = sm + FB_QS;
    float* Ks  = sm + FB_KS;
    float* Es  = sm + FB_ES;
    float* Vs  = sm + FB_VS;
    float* inv = sm + FB_INV;

    int tid = threadIdx.x, wid = tid >> 5, lane = tid & 31;
    int gr = lane >> 2, tq = lane & 3;
    int warpm = wid & 3, warpn = wid >> 2;
    int r0 = blockIdx.x * 128, bh = blockIdx.y;

    const float* qh  = g_q  + ((size_t)bh * T_ + r0) * HD;
    const float* kh  = g_k  + (size_t)bh * T_ * HD;
    const float* vtb = g_vt + (size_t)bh * HD * T_;
    float* wbase = wts + ((size_t)bh * T_ + r0) * T_;

    if (tid < 128) inv[tid] = 1.f / g_rowsum[(size_t)bh * T_ + r0 + tid];

    auto loadK = [&](int c) {
        float* dst = Ks + (size_t)(c & 1) * 128 * 68;
        #pragma unroll
        for (int p = 0; p < 8; p++) {
            int idx = tid + p * 256;
            int r = idx >> 4, c4 = idx & 15;
            cpa16(s2u(&dst[r * 68 + c4 * 4]), kh + (size_t)(c * 128 + r) * HD + c4 * 4);
        }
        cpcommit();
    };
    auto loadV = [&](int c) {
        #pragma unroll
        for (int p = 0; p < 8; p++) {
            int idx = tid + p * 256;
            int r = idx >> 5, c4 = idx & 31;
            cpa16(s2u(&Vs[r * 132 + c4 * 4]), vtb + (size_t)r * T_ + c * 128 + c4 * 4);
        }
        cpcommit();
    };

    #pragma unroll
    for (int p = 0; p < 8; p++) {
        int idx = tid + p * 256;
        int r = idx >> 4, c4 = idx & 15;
        cpa16(s2u(&Qs[r * 68 + c4 * 4]), qh + (size_t)r * HD + c4 * 4);
    }
    {
        float* dst = Ks;
        #pragma unroll
        for (int p = 0; p < 8; p++) {
            int idx = tid + p * 256;
            int r = idx >> 4, c4 = idx & 15;
            cpa16(s2u(&dst[r * 68 + c4 * 4]), kh + (size_t)r * HD + c4 * 4);
        }
    }
    cpcommit();

    float acco[2][4][4];
    #pragma unroll
    for (int i = 0; i < 2; i++)
        #pragma unroll
        for (int j = 0; j < 4; j++)
            #pragma unroll
            for (int q = 0; q < 4; q++) acco[i][j][q] = 0.f;

    for (int c = 0; c < 16; c++) {
        cpwait<0>();
        __syncthreads();             // Ks[c] visible; Es/Vs free; inv ready
        loadV(c);
        if (c < 15) loadK(c + 1);

        const float* Kb = Ks + (size_t)(c & 1) * 128 * 68;

        // ---- QK^T ----
        float acc[2][8][4];
        #pragma unroll
        for (int i = 0; i < 2; i++)
            #pragma unroll
            for (int j = 0; j < 8; j++)
                #pragma unroll
                for (int q = 0; q < 4; q++) acc[i][j][q] = 0.f;

        #pragma unroll
        for (int k8 = 0; k8 < 64; k8 += 8) {
            uint32_t a[2][4];
            #pragma unroll
            for (int i = 0; i < 2; i++) {
                int r = warpm * 32 + i * 16 + gr;
                int cc = k8 + tq;
                a[i][0] = __float_as_uint(Qs[r * 68 + cc]);
                a[i][1] = __float_as_uint(Qs[(r + 8) * 68 + cc]);
                a[i][2] = __float_as_uint(Qs[r * 68 + cc + 4]);
                a[i][3] = __float_as_uint(Qs[(r + 8) * 68 + cc + 4]);
            }
            #pragma unroll
            for (int j = 0; j < 8; j++) {
                int nb = warpn * 64 + j * 8 + gr;
                uint32_t b[2];
                b[0] = __float_as_uint(Kb[nb * 68 + k8 + tq]);
                b[1] = __float_as_uint(Kb[nb * 68 + k8 + 4 + tq]);
                mma8(acc[0][j], a[0], b);
                mma8(acc[1][j], a[1], b);
            }
        }

        // ---- w = exp*inv -> Es (exact, smem only) ----
        #pragma unroll
        for (int i = 0; i < 2; i++) {
            #pragma unroll
            for (int half = 0; half < 2; half++) {
                int lr = warpm * 32 + i * 16 + gr + half * 8;
                float iv = inv[lr];
                #pragma unroll
                for (int j = 0; j < 8; j++) {
                    int col = warpn * 64 + j * 8 + 2 * tq;
                    float w0 = __expf(0.125f * acc[i][j][half * 2 + 0]) * iv;
                    float w1 = __expf(0.125f * acc[i][j][half * 2 + 1]) * iv;
                    *(float2*)&Es[lr * ESS + col] = make_float2(w0, w1);
                }
            }
        }

        if (c < 15) cpwait<1>(); else cpwait<0>();   // V[c] arrived
        __syncthreads();                              // Es + Vs visible

        // ---- coalesced W store: one row per warp-iteration ----
        #pragma unroll
        for (int rr = 0; rr < 16; rr++) {
            int row = wid * 16 + rr;
            float4 v = *(float4*)&Es[row * ESS + lane * 4];
            *(float4*)&wbase[(size_t)row * T_ + c * 128 + lane * 4] = v;
        }

        // ---- O += Es @ V (Es raw fp32 bits consumed as tf32) ----
        #pragma unroll
        for (int k8 = 0; k8 < 128; k8 += 8) {
            uint32_t a[2][4];
            #pragma unroll
            for (int i = 0; i < 2; i++) {
                int r = warpm * 32 + i * 16 + gr;
                int cc = k8 + tq;
                a[i][0] = __float_as_uint(Es[r * ESS + cc]);
                a[i][1] = __float_as_uint(Es[(r + 8) * ESS + cc]);
                a[i][2] = __float_as_uint(Es[r * ESS + cc + 4]);
                a[i][3] = __float_as_uint(Es[(r + 8) * ESS + cc + 4]);
            }
            #pragma unroll
            for (int j = 0; j < 4; j++) {
                int nb = warpn * 32 + j * 8 + gr;
                uint32_t b[2];
                b[0] = __float_as_uint(Vs[nb * 132 + k8 + tq]);
                b[1] = __float_as_uint(Vs[nb * 132 + k8 + 4 + tq]);
                mma8(acco[0][j], a[0], b);
                mma8(acco[1][j], a[1], b);
            }
        }
    }

    // ---- epilogue: O -> g_ao (tf32) ----
    int b = bh >> 4, h = bh & 15;
    #pragma unroll
    for (int i = 0; i < 2; i++) {
        #pragma unroll
        for (int half = 0; half < 2; half++) {
            int t = r0 + warpm * 32 + i * 16 + gr + half * 8;
            float* orow = g_ao + (size_t)(b * T_ + t) * D_MODEL + h * HD;
            #pragma unroll
            for (int j = 0; j < 4; j++) {
                int dd = warpn * 32 + j * 8 + 2 * tq;
                *(float2*)&orow[dd] = make_float2(
                    f2tf(acco[i][j][half * 2 + 0]), f2tf(acco[i][j][half * 2 + 1]));
            }
        }
    }
}

// ===========================================================================
extern "C" void kernel_launch(void* const* d_in, const int* in_sizes, int n_in,
                              void* d_out, int out_size) {
    const float* x    = (const float*)d_in[0];
    const float* Wqkv = (const float*)d_in[1];
    const float* bqkv = (const float*)d_in[2];
    const float* Wo   = (const float*)d_in[3];
    const float* bo   = (const float*)d_in[4];

    float* y   = (float*)d_out;                         // [B,T,D]
    float* wts = (float*)d_out + (size_t)BT * D_MODEL;  // [B,H,T,T]

    const int GB_SMEM = 2 * 3 * 128 * GBS * 4;          // 110592
    const int RS_SMEM = 3 * 128 * 68 * 4;               // 104448
    const int FB_SMEM = FB_FLTS * 4;
    cudaFuncSetAttribute(gemm_big<0>, cudaFuncAttributeMaxDynamicSharedMemorySize, GB_SMEM);
    cudaFuncSetAttribute(gemm_big<1>, cudaFuncAttributeMaxDynamicSharedMemorySize, GB_SMEM);
    cudaFuncSetAttribute(attn_rowsum, cudaFuncAttributeMaxDynamicSharedMemorySize, RS_SMEM);
    cudaFuncSetAttribute(attn_fused,  cudaFuncAttributeMaxDynamicSharedMemorySize, FB_SMEM);

    float *wt_p = nullptr, *wot_p = nullptr, *ao_p = nullptr, *x_p = nullptr;
    cudaGetSymbolAddress((void**)&wt_p,  g_wt);
    cudaGetSymbolAddress((void**)&wot_p, g_wot);
    cudaGetSymbolAddress((void**)&ao_p,  g_ao);
    cudaGetSymbolAddress((void**)&x_p,   g_x);

    cvt_x<<<BT * D_MODEL / 1024, 256>>>(x);   // also zeroes g_rowsum
    transpose_w<<<dim3(96, 32), dim3(32, 8)>>>(Wqkv, wt_p, 1024, 3072);
    transpose_w<<<dim3(32, 32), dim3(32, 8)>>>(Wo, wot_p, 1024, 1024);

    gemm_big<0><<<dim3(24, 32), 256, GB_SMEM>>>(x_p, wt_p, bqkv, nullptr);
    transpose_v<<<dim3(2, 64, 32), dim3(32, 8)>>>();

    attn_rowsum<<<dim3(16, 32), 256, RS_SMEM>>>();
    attn_fused<<<dim3(16, 32), 256, FB_SMEM>>>(wts);

    gemm_big<1><<<dim3(8, 32), 256, GB_SMEM>>>(ao_p, wot_p, bo, y);
}